// round 10
// baseline (speedup 1.0000x reference)
#include <cuda_runtime.h>
#include <cuda_bf16.h>
#include <math_constants.h>
#include <cstdint>

// Problem constants
#define Bq   4
#define Nq   4096
#define Kq   9
#define BNT  16384           // B*N
#define CNT_EDGE 147456.0f   // B*N*K
#define STG  4               // cp.async pipeline stages
#define STGB 24576           // bytes per stage (4 planes x 128 rows x 48B)

// ------------------------- scratch (device globals; no allocs) -------------
__device__ float g_ab[(size_t)BNT * 512];     // GEMM out [A | Bm]
__device__ int   g_idx[BNT * Kq];
__device__ float g_wc[256 * 512];             // f32 weights (decoder gemm_sm)
__device__ float g_ymax[(size_t)BNT * 256];
__device__ float g_ymin[(size_t)BNT * 256];
__device__ float g_act1[(size_t)BNT * 64];    // out1 f32 (decoder input)
__device__ float g_low[(size_t)BNT * 48];
__device__ float g_fused[(size_t)BNT * 256];
__device__ float g_stats[1024];
__device__ float g_h[Bq * 512];
__device__ float g_h2[Bq * 256];
__device__ float g_hpart[2][Bq][32][256];
// bf16 split planes (hi/lo): activations row-major [m][Kp], Kp mult of 16
__device__ __nv_bfloat16 g_ph[(size_t)BNT * 256];
__device__ __nv_bfloat16 g_pl[(size_t)BNT * 256];
__device__ __nv_bfloat16 g_lowh[(size_t)BNT * 48];
__device__ __nv_bfloat16 g_lowl[(size_t)BNT * 48];
// weights n-major [n][Kp]
__device__ __nv_bfloat16 g_wbh[512 * 256];
__device__ __nv_bfloat16 g_wbl[512 * 256];

// ------------------------- helpers -----------------------------------------
__device__ __forceinline__ uint32_t sptr(const void* p)
{
    return (uint32_t)__cvta_generic_to_shared(p);
}

#define CPA16(dst, src) \
    asm volatile("cp.async.cg.shared.global [%0], [%1], 16;" \
                 :: "r"(dst), "l"(src) : "memory")
#define CPA_COMMIT() asm volatile("cp.async.commit_group;" ::: "memory")
#define CPA_WAIT2()  asm volatile("cp.async.wait_group 2;" ::: "memory")
#define LDSM4(r0, r1, r2, r3, addr) \
    asm volatile("ldmatrix.sync.aligned.m8n8.x4.shared.b16 {%0,%1,%2,%3}, [%4];" \
                 : "=r"(r0), "=r"(r1), "=r"(r2), "=r"(r3) : "r"(addr))
#define MMA4(CC, AA, B0, B1) \
    asm volatile("mma.sync.aligned.m16n8k16.row.col.f32.bf16.bf16.f32 " \
                 "{%0,%1,%2,%3}, {%4,%5,%6,%7}, {%8,%9}, {%0,%1,%2,%3};" \
                 : "+f"(CC[0]), "+f"(CC[1]), "+f"(CC[2]), "+f"(CC[3]) \
                 : "r"(AA[0]), "r"(AA[1]), "r"(AA[2]), "r"(AA[3]), \
                   "r"(B0), "r"(B1))

__device__ __forceinline__ void bf16_split(float v, __nv_bfloat16& h,
                                           __nv_bfloat16& l)
{
    h = __float2bfloat16(v);
    l = __float2bfloat16(v - __bfloat162float(h));
}

// ------------------------- transpose x -> bf16 planes (Kp=16) --------------
__global__ void transpose_kernel(const float* __restrict__ x)
{
    int i = blockIdx.x * blockDim.x + threadIdx.x;
    if (i < BNT * 16) {
        int k  = i & 15;
        int bn = i >> 4;
        int b  = bn >> 12;
        int n  = bn & (Nq - 1);
        float v = (k < 3) ? x[((size_t)b * 3 + k) * Nq + n] : 0.f;
        __nv_bfloat16 h, l;
        bf16_split(v, h, l);
        g_ph[i] = h; g_pl[i] = l;
    }
}

// ------------------------- KNN: top-9, split-m with merge ------------------
__global__ __launch_bounds__(256) void knn_kernel(const float* __restrict__ x)
{
    __shared__ float sx0[Nq];
    __shared__ float sx1[Nq];
    __shared__ float sx2[Nq];
    int tid = threadIdx.x;
    int b = blockIdx.x >> 5;
    int rowBase = (blockIdx.x & 31) * 128;
    const float* xb = x + (size_t)b * 3 * Nq;
    for (int t = tid; t < Nq; t += 256) {
        sx0[t] = xb[t];
        sx1[t] = xb[Nq + t];
        sx2[t] = xb[2 * Nq + t];
    }
    __syncthreads();

    int half = tid >> 7;
    int pt   = tid & 127;
    int n = rowBase + pt;
    float a0 = sx0[n], a1 = sx1[n], a2 = sx2[n];
    float an = a0 * a0 + a1 * a1 + a2 * a2;

    float bd[9]; int bi[9];
    #pragma unroll
    for (int j = 0; j < 9; j++) { bd[j] = CUDART_INF_F; bi[j] = 0; }

    int mS = half * 2048, mE = mS + 2048;
    for (int m = mS; m < mE; m++) {
        float c0 = sx0[m], c1 = sx1[m], c2 = sx2[m];
        float cn = c0 * c0 + c1 * c1 + c2 * c2;
        float dt = a0 * c0 + a1 * c1 + a2 * c2;
        float d  = an + cn - 2.f * dt;
        if (m == n) d = CUDART_INF_F;
        if (d < bd[8]) {
            bd[8] = d; bi[8] = m;
            #pragma unroll
            for (int j = 8; j > 0; --j) {
                if (bd[j] < bd[j - 1]) {
                    float td = bd[j]; bd[j] = bd[j - 1]; bd[j - 1] = td;
                    int   ti = bi[j]; bi[j] = bi[j - 1]; bi[j - 1] = ti;
                }
            }
        }
    }
    __syncthreads();
    float* cd = sx0;
    int*   ci = (int*)sx1;
    if (half) {
        #pragma unroll
        for (int j = 0; j < 9; j++) { cd[pt * 9 + j] = bd[j]; ci[pt * 9 + j] = bi[j]; }
    }
    __syncthreads();
    if (!half) {
        #pragma unroll
        for (int j = 0; j < 9; j++) {
            float d = cd[pt * 9 + j]; int im = ci[pt * 9 + j];
            if (d < bd[8]) {
                bd[8] = d; bi[8] = im;
                #pragma unroll
                for (int jj = 8; jj > 0; --jj) {
                    if (bd[jj] < bd[jj - 1]) {
                        float td = bd[jj]; bd[jj] = bd[jj - 1]; bd[jj - 1] = td;
                        int   ti = bi[jj]; bi[jj] = bi[jj - 1]; bi[jj - 1] = ti;
                    }
                }
            }
        }
        int* op = g_idx + ((size_t)b * Nq + n) * Kq;
        #pragma unroll
        for (int j = 0; j < 9; j++) op[j] = bi[j];
    }
}

// ------------------------- weight prep (bf16 n-major planes) ---------------
__global__ void prep_edge_wb(const float* __restrict__ W, int Cin, int Cout,
                             int Kp)
{
    int i = blockIdx.x * blockDim.x + threadIdx.x;
    if (i < 2 * Cout * Kp) {
        int n = i / Kp, c = i % Kp;
        float v = 0.f;
        if (c < Cin)
            v = (n < Cout)
              ? W[(size_t)n * 2 * Cin + c] - W[(size_t)n * 2 * Cin + Cin + c]
              : W[(size_t)(n - Cout) * 2 * Cin + Cin + c];
        __nv_bfloat16 h, l;
        bf16_split(v, h, l);
        g_wbh[i] = h; g_wbl[i] = l;
    }
}

__global__ void prep_plain_wb(const float* __restrict__ W, int Cin, int Cout,
                              int rowStride, int colOff, int Kp)
{
    int i = blockIdx.x * blockDim.x + threadIdx.x;
    if (i < Cout * Kp) {
        int n = i / Kp, c = i % Kp;
        float v = (c < Cin) ? W[(size_t)n * rowStride + colOff + c] : 0.f;
        __nv_bfloat16 h, l;
        bf16_split(v, h, l);
        g_wbh[i] = h; g_wbl[i] = l;
    }
}

__global__ void prep_plain_w(const float* __restrict__ W, int Cin, int Cout,
                             int rowStride, int colOff)
{
    int i = blockIdx.x * blockDim.x + threadIdx.x;
    if (i < Cin * Cout) {
        int c = i / Cout, o = i % Cout;
        g_wc[(size_t)c * Cout + o] = W[(size_t)o * rowStride + colOff + c];
    }
}

// ------------------------- cp.async 4-stage split-bf16 GEMM ----------------
// C(M,N) = A(M,Kp) * B(Kp,N);  A planes row-major, B planes n-major.
// 3 terms: Ah*Bh + Al*Bh + Ah*Bl.  Block 128x128, 512 thr = 16 warps (4m x 4n),
// warp tile 32x32.  Stage k16, SMEM rows padded to 48B.
__global__ __launch_bounds__(512) void gemm_async(
    const __nv_bfloat16* __restrict__ Ah,
    const __nv_bfloat16* __restrict__ Al,
    float* __restrict__ C, int Kp, int N, int acc)
{
    extern __shared__ __nv_bfloat16 dsm[];
    uint32_t sm0 = sptr(dsm);

    int tid = threadIdx.x, lane = tid & 31, wid = tid >> 5;
    int warp_m = wid & 3, warp_n = wid >> 2;
    int m0 = blockIdx.y * 128, n0 = blockIdx.x * 128;
    int g = lane >> 2, t4 = lane & 3;

    float c[2][4][4];
    #pragma unroll
    for (int i = 0; i < 2; i++)
        #pragma unroll
        for (int j = 0; j < 4; j++)
            #pragma unroll
            for (int r = 0; r < 4; r++) c[i][j][r] = 0.f;

    int nch = Kp >> 4;

    int lrow = lane & 15, koffB = (lane >> 4) * 16;
    uint32_t aoff[2], boff[2];
    #pragma unroll
    for (int i = 0; i < 2; i++)
        aoff[i] = (warp_m * 32 + i * 16 + lrow) * 48 + koffB;
    #pragma unroll
    for (int q = 0; q < 2; q++)
        boff[q] = (warp_n * 32 + q * 16 + lrow) * 48 + koffB;

    // fill: 1024 items (4 planes x 128 rows x 2 halves), 2 per thread
    auto fill_stage = [&](int s, int ch) {
        int k0 = ch * 16;
        #pragma unroll
        for (int t = 0; t < 2; t++) {
            int it = tid + t * 512;
            int c2 = it & 1, row = (it >> 1) & 127, pln = it >> 8;
            const __nv_bfloat16* src;
            if (pln == 0)      src = Ah    + (size_t)(m0 + row) * Kp + k0 + c2 * 8;
            else if (pln == 1) src = Al    + (size_t)(m0 + row) * Kp + k0 + c2 * 8;
            else if (pln == 2) src = g_wbh + (size_t)(n0 + row) * Kp + k0 + c2 * 8;
            else               src = g_wbl + (size_t)(n0 + row) * Kp + k0 + c2 * 8;
            CPA16(sm0 + s * STGB + pln * 6144 + row * 48 + c2 * 16, src);
        }
        CPA_COMMIT();
    };

    #pragma unroll
    for (int s = 0; s < STG - 1; s++) {
        if (s < nch) fill_stage(s, s);
        else CPA_COMMIT();
    }

    for (int ch = 0; ch < nch; ch++) {
        int s = ch % STG;
        CPA_WAIT2();
        __syncthreads();
        int pre = ch + STG - 1;
        if (pre < nch) fill_stage(pre % STG, pre);
        else CPA_COMMIT();

        uint32_t sAs = sm0 + s * STGB, sBs = sAs + 12288;
        uint32_t ah[2][4], al[2][4];
        #pragma unroll
        for (int i = 0; i < 2; i++) {
            LDSM4(ah[i][0], ah[i][1], ah[i][2], ah[i][3], sAs + aoff[i]);
            LDSM4(al[i][0], al[i][1], al[i][2], al[i][3], sAs + 6144 + aoff[i]);
        }
        #pragma unroll
        for (int q = 0; q < 2; q++) {
            uint32_t bh0, bh1, bh2, bh3, bl0, bl1, bl2, bl3;
            LDSM4(bh0, bh1, bh2, bh3, sBs + boff[q]);
            LDSM4(bl0, bl1, bl2, bl3, sBs + 6144 + boff[q]);
            int j0 = q * 2, j1 = q * 2 + 1;
            MMA4(c[0][j0], ah[0], bh0, bh2);
            MMA4(c[0][j0], al[0], bh0, bh2);
            MMA4(c[0][j0], ah[0], bl0, bl2);
            MMA4(c[1][j0], ah[1], bh0, bh2);
            MMA4(c[1][j0], al[1], bh0, bh2);
            MMA4(c[1][j0], ah[1], bl0, bl2);
            MMA4(c[0][j1], ah[0], bh1, bh3);
            MMA4(c[0][j1], al[0], bh1, bh3);
            MMA4(c[0][j1], ah[0], bl1, bl3);
            MMA4(c[1][j1], ah[1], bh1, bh3);
            MMA4(c[1][j1], al[1], bh1, bh3);
            MMA4(c[1][j1], ah[1], bl1, bl3);
        }
    }

    #pragma unroll
    for (int i = 0; i < 2; i++) {
        int m = m0 + warp_m * 32 + i * 16 + g;
        #pragma unroll
        for (int j = 0; j < 4; j++) {
            int n = n0 + warp_n * 32 + j * 8 + t4 * 2;
            float2* p0 = (float2*)&C[(size_t)m * N + n];
            float2* p1 = (float2*)&C[(size_t)(m + 8) * N + n];
            if (acc) {
                float2 v0 = *p0, v1 = *p1;
                v0.x += c[i][j][0]; v0.y += c[i][j][1];
                v1.x += c[i][j][2]; v1.y += c[i][j][3];
                *p0 = v0; *p1 = v1;
            } else {
                *p0 = make_float2(c[i][j][0], c[i][j][1]);
                *p1 = make_float2(c[i][j][2], c[i][j][3]);
            }
        }
    }
}

// ------------------------- small FFMA GEMM (decoder, N=48) -----------------
__global__ __launch_bounds__(256) void gemm_sm(const float* __restrict__ X,
                                               float* __restrict__ C,
                                               int K, int N)
{
    __shared__ float sX[16][65];
    __shared__ float sW[16][64];
    int tx = threadIdx.x, ty = threadIdx.y;
    int tid = ty * 16 + tx;
    int m0 = blockIdx.y * 64;
    int n0 = blockIdx.x * 64;

    float accum[4][4];
    #pragma unroll
    for (int i = 0; i < 4; i++)
        #pragma unroll
        for (int j = 0; j < 4; j++) accum[i][j] = 0.f;

    for (int k0 = 0; k0 < K; k0 += 16) {
        for (int t = tid; t < 64 * 16; t += 256) {
            int m = t >> 4, k = t & 15;
            sX[k][m] = (k0 + k < K) ? X[(size_t)(m0 + m) * K + k0 + k] : 0.f;
        }
        for (int t = tid; t < 16 * 64; t += 256) {
            int k = t >> 6, n = t & 63;
            sW[k][n] = (k0 + k < K && n0 + n < N)
                     ? g_wc[(size_t)(k0 + k) * N + n0 + n] : 0.f;
        }
        __syncthreads();
        #pragma unroll
        for (int kk = 0; kk < 16; kk++) {
            float xr[4], wr[4];
            #pragma unroll
            for (int i = 0; i < 4; i++) xr[i] = sX[kk][ty * 4 + i];
            #pragma unroll
            for (int j = 0; j < 4; j++) wr[j] = sW[kk][tx * 4 + j];
            #pragma unroll
            for (int i = 0; i < 4; i++)
                #pragma unroll
                for (int j = 0; j < 4; j++)
                    accum[i][j] = fmaf(xr[i], wr[j], accum[i][j]);
        }
        __syncthreads();
    }
    #pragma unroll
    for (int i = 0; i < 4; i++) {
        int m = m0 + ty * 4 + i;
        #pragma unroll
        for (int j = 0; j < 4; j++) {
            int n = n0 + tx * 4 + j;
            if (n < N) C[(size_t)m * N + n] = accum[i][j];
        }
    }
}

// ------------------------- gather-max/min + BN stats -----------------------
#define GN 64
__global__ void gather_kernel(int Cout)
{
    __shared__ int sidx[GN * Kq];
    int n0 = blockIdx.x * GN;
    for (int t = threadIdx.x; t < GN * Kq; t += blockDim.x)
        sidx[t] = g_idx[(size_t)n0 * Kq + t];
    __syncthreads();

    int o  = threadIdx.x;
    int C2 = 2 * Cout;
    float lsum = 0.f, lssq = 0.f;
    for (int g = 0; g < GN; g++) {
        int bn = n0 + g;
        int bbase = (bn >> 12) << 12;
        float a = g_ab[(size_t)bn * C2 + o];
        float mx = -CUDART_INF_F, mn = CUDART_INF_F, s = 0.f, sq = 0.f;
        #pragma unroll
        for (int k = 0; k < Kq; k++) {
            int j = sidx[g * Kq + k];
            float v = g_ab[(size_t)(bbase + j) * C2 + Cout + o];
            mx = fmaxf(mx, v); mn = fminf(mn, v);
            s += v; sq = fmaf(v, v, sq);
        }
        g_ymax[(size_t)bn * Cout + o] = a + mx;
        g_ymin[(size_t)bn * Cout + o] = a + mn;
        lsum += fmaf((float)Kq, a, s);
        lssq += (float)Kq * a * a + 2.f * a * s + sq;
    }
    atomicAdd(&g_stats[o], lsum);
    atomicAdd(&g_stats[512 + o], lssq);
}

// ------------------------- column stats (decoder BN) -----------------------
__global__ void colstats_kernel(const float* __restrict__ Y, int C, int Mrows)
{
    __shared__ float ss[256];
    __shared__ float sq[256];
    int o = blockIdx.x;
    float s = 0.f, q = 0.f;
    for (int m = threadIdx.x; m < Mrows; m += 256) {
        float v = Y[(size_t)m * C + o];
        s += v; q = fmaf(v, v, q);
    }
    ss[threadIdx.x] = s; sq[threadIdx.x] = q;
    __syncthreads();
    for (int st = 128; st; st >>= 1) {
        if (threadIdx.x < st) {
            ss[threadIdx.x] += ss[threadIdx.x + st];
            sq[threadIdx.x] += sq[threadIdx.x + st];
        }
        __syncthreads();
    }
    if (threadIdx.x == 0) { g_stats[o] = ss[0]; g_stats[512 + o] = sq[0]; }
}

// ------------------------- BN + ReLU (+ max-select) + plane split ----------
__global__ void bnrelu_kernel(const float* __restrict__ ymax,
                              const float* __restrict__ ymin,
                              const float* __restrict__ gg,
                              const float* __restrict__ bb,
                              float* __restrict__ outp,
                              __nv_bfloat16* __restrict__ ph,
                              __nv_bfloat16* __restrict__ pl,
                              int C, float invCnt, int total)
{
    for (int i = blockIdx.x * blockDim.x + threadIdx.x; i < total;
         i += gridDim.x * blockDim.x) {
        int o = i % C;
        float mean = g_stats[o] * invCnt;
        float var  = fmaf(-mean, mean, g_stats[512 + o] * invCnt);
        float sc   = gg[o] * rsqrtf(var + 1e-5f);
        float sh   = fmaf(-mean, sc, bb[o]);
        float y    = (sc >= 0.f) ? ymax[i] : ymin[i];
        float r    = fmaxf(fmaf(sc, y, sh), 0.f);
        if (outp) outp[i] = r;
        __nv_bfloat16 h, l;
        bf16_split(r, h, l);
        ph[i] = h; pl[i] = l;
    }
}

// ------------------------- global max/mean pool (2-stage) ------------------
__global__ void hreduce1_kernel()
{
    int b = blockIdx.y, chunk = blockIdx.x, o = threadIdx.x;
    const float* f = g_fused + ((size_t)b * Nq + chunk * 128) * 256 + o;
    float mx = -CUDART_INF_F, s = 0.f;
    for (int n = 0; n < 128; n++) {
        float v = f[(size_t)n * 256];
        mx = fmaxf(mx, v); s += v;
    }
    g_hpart[0][b][chunk][o] = mx;
    g_hpart[1][b][chunk][o] = s;
}

__global__ void hreduce2_kernel()
{
    int b = blockIdx.x, o = threadIdx.x;
    float mx = -CUDART_INF_F, s = 0.f;
    #pragma unroll
    for (int c = 0; c < 32; c++) {
        mx = fmaxf(mx, g_hpart[0][b][c][o]);
        s += g_hpart[1][b][c][o];
    }
    g_h[b * 512 + o]       = mx;
    g_h[b * 512 + 256 + o] = s * (1.f / Nq);
}

// ------------------------- classifier head ---------------------------------
__global__ void cls1_kernel(const float* __restrict__ W,
                            const float* __restrict__ gg,
                            const float* __restrict__ bb)
{
    int o = threadIdx.x;
    float y[4];
    #pragma unroll
    for (int b = 0; b < 4; b++) {
        float s = 0.f;
        const float* wr = W + (size_t)o * 512;
        const float* hr = g_h + b * 512;
        for (int c = 0; c < 512; c++) s = fmaf(wr[c], hr[c], s);
        y[b] = s;
    }
    float mean = 0.25f * (y[0] + y[1] + y[2] + y[3]);
    float ssq  = y[0]*y[0] + y[1]*y[1] + y[2]*y[2] + y[3]*y[3];
    float var  = fmaf(-mean, mean, 0.25f * ssq);
    float sc   = gg[o] * rsqrtf(var + 1e-5f);
    float sh   = fmaf(-mean, sc, bb[o]);
    #pragma unroll
    for (int b = 0; b < 4; b++)
        g_h2[b * 256 + o] = fmaxf(fmaf(sc, y[b], sh), 0.f);
}

__global__ void cls2_kernel(const float* __restrict__ W, float* __restrict__ out)
{
    int t = threadIdx.x;
    if (t < 160) {
        int b = t / 40, o = t % 40;
        float s = 0.f;
        for (int c = 0; c < 256; c++)
            s = fmaf(W[(size_t)o * 256 + c], g_h2[b * 256 + c], s);
        out[b * 40 + o] = s;
    }
}

// ------------------------- host launch sequence ----------------------------
extern "C" void kernel_launch(void* const* d_in, const int* in_sizes, int n_in,
                              void* d_out, int out_size)
{
    const float* x     = (const float*)d_in[0];
    const float* w1    = (const float*)d_in[2];
    const float* g1    = (const float*)d_in[3];
    const float* b1    = (const float*)d_in[4];
    const float* w2    = (const float*)d_in[5];
    const float* g2    = (const float*)d_in[6];
    const float* b2    = (const float*)d_in[7];
    const float* w3    = (const float*)d_in[8];
    const float* g3    = (const float*)d_in[9];
    const float* b3    = (const float*)d_in[10];
    const float* w4    = (const float*)d_in[11];
    const float* g4    = (const float*)d_in[12];
    const float* b4    = (const float*)d_in[13];
    const float* dec_w = (const float*)d_in[14];
    const float* dec_g = (const float*)d_in[15];
    const float* dec_b = (const float*)d_in[16];
    const float* fus_w = (const float*)d_in[17];
    const float* cw1   = (const float*)d_in[18];
    const float* cg    = (const float*)d_in[19];
    const float* cb    = (const float*)d_in[20];
    const float* cw2   = (const float*)d_in[21];
    float* out = (float*)d_out;

    static int smem_set = 0;
    if (!smem_set) {
        cudaFuncSetAttribute(gemm_async,
            cudaFuncAttributeMaxDynamicSharedMemorySize, STG * STGB);
        smem_set = 1;
    }
    const int GSM = STG * STGB;   // 98304 B dynamic smem

    void *p_ab, *p_ymax, *p_ymin, *p_act1, *p_low, *p_fused, *p_stats,
         *p_ph, *p_pl, *p_lowh, *p_lowl;
    cudaGetSymbolAddress(&p_ab,    g_ab);
    cudaGetSymbolAddress(&p_ymax,  g_ymax);
    cudaGetSymbolAddress(&p_ymin,  g_ymin);
    cudaGetSymbolAddress(&p_act1,  g_act1);
    cudaGetSymbolAddress(&p_low,   g_low);
    cudaGetSymbolAddress(&p_fused, g_fused);
    cudaGetSymbolAddress(&p_stats, g_stats);
    cudaGetSymbolAddress(&p_ph,    g_ph);
    cudaGetSymbolAddress(&p_pl,    g_pl);
    cudaGetSymbolAddress(&p_lowh,  g_lowh);
    cudaGetSymbolAddress(&p_lowl,  g_lowl);

    const __nv_bfloat16* ph = (const __nv_bfloat16*)p_ph;
    const __nv_bfloat16* pl = (const __nv_bfloat16*)p_pl;
    const float invEdge = 1.f / CNT_EDGE;
    const dim3 tb16(16, 16);

    transpose_kernel<<<(BNT * 16 + 255) / 256, 256>>>(x);
    knn_kernel<<<128, 256>>>(x);

    // ---- EdgeConv 1: Cin=3 (Kp=16), Cout=64 (N=128) ----
    prep_edge_wb<<<(128 * 16 + 255) / 256, 256>>>(w1, 3, 64, 16);
    gemm_async<<<dim3(1, 128), 512, GSM>>>(ph, pl, (float*)p_ab, 16, 128, 0);
    cudaMemsetAsync(p_stats, 0, 1024 * sizeof(float));
    gather_kernel<<<BNT / GN, 64>>>(64);
    bnrelu_kernel<<<(BNT * 64 + 255) / 256, 256>>>((const float*)p_ymax,
        (const float*)p_ymin, g1, b1, (float*)p_act1,
        (__nv_bfloat16*)p_ph, (__nv_bfloat16*)p_pl, 64, invEdge, BNT * 64);

    // ---- EdgeConv 2: Cin=64, Cout=128 (N=256) ----
    prep_edge_wb<<<(256 * 64 + 255) / 256, 256>>>(w2, 64, 128, 64);
    gemm_async<<<dim3(2, 128), 512, GSM>>>(ph, pl, (float*)p_ab, 64, 256, 0);
    cudaMemsetAsync(p_stats, 0, 1024 * sizeof(float));
    gather_kernel<<<BNT / GN, 128>>>(128);
    bnrelu_kernel<<<(BNT * 128 + 255) / 256, 256>>>((const float*)p_ymax,
        (const float*)p_ymin, g2, b2, nullptr,
        (__nv_bfloat16*)p_ph, (__nv_bfloat16*)p_pl, 128, invEdge, BNT * 128);

    // ---- EdgeConv 3: Cin=128, Cout=256 (N=512) ----
    prep_edge_wb<<<(512 * 128 + 255) / 256, 256>>>(w3, 128, 256, 128);
    gemm_async<<<dim3(4, 128), 512, GSM>>>(ph, pl, (float*)p_ab, 128, 512, 0);
    cudaMemsetAsync(p_stats, 0, 1024 * sizeof(float));
    gather_kernel<<<BNT / GN, 256>>>(256);
    bnrelu_kernel<<<(BNT * 256 + 255) / 256, 256>>>((const float*)p_ymax,
        (const float*)p_ymin, g3, b3, nullptr,
        (__nv_bfloat16*)p_ph, (__nv_bfloat16*)p_pl, 256, invEdge, BNT * 256);

    // ---- EdgeConv 4: Cin=256, Cout=256 (N=512) ----
    prep_edge_wb<<<(512 * 256 + 255) / 256, 256>>>(w4, 256, 256, 256);
    gemm_async<<<dim3(4, 128), 512, GSM>>>(ph, pl, (float*)p_ab, 256, 512, 0);
    cudaMemsetAsync(p_stats, 0, 1024 * sizeof(float));
    gather_kernel<<<BNT / GN, 256>>>(256);
    bnrelu_kernel<<<(BNT * 256 + 255) / 256, 256>>>((const float*)p_ymax,
        (const float*)p_ymin, g4, b4, nullptr,
        (__nv_bfloat16*)p_ph, (__nv_bfloat16*)p_pl, 256, invEdge, BNT * 256);
    // g_ph/g_pl now hold out4 planes (Kp=256)

    // ---- decoder: low = relu(bn(dec_w @ out1)) ----
    prep_plain_w<<<(64 * 48 + 255) / 256, 256>>>(dec_w, 64, 48, 64, 0);
    gemm_sm<<<dim3(1, 256), tb16>>>((const float*)p_act1, (float*)p_low, 64, 48);
    colstats_kernel<<<48, 256>>>((const float*)p_low, 48, BNT);
    bnrelu_kernel<<<(BNT * 48 + 255) / 256, 256>>>((const float*)p_low,
        (const float*)p_low, dec_g, dec_b, nullptr,
        (__nv_bfloat16*)p_lowh, (__nv_bfloat16*)p_lowl, 48, 1.f / BNT, BNT * 48);

    // ---- fusion: fused = fus_w @ concat([out4, low]) ----
    prep_plain_wb<<<(256 * 256 + 255) / 256, 256>>>(fus_w, 256, 256, 304, 0, 256);
    gemm_async<<<dim3(2, 128), 512, GSM>>>(ph, pl, (float*)p_fused, 256, 256, 0);
    prep_plain_wb<<<(256 * 48 + 255) / 256, 256>>>(fus_w, 48, 256, 304, 256, 48);
    gemm_async<<<dim3(2, 128), 512, GSM>>>((const __nv_bfloat16*)p_lowh,
        (const __nv_bfloat16*)p_lowl, (float*)p_fused, 48, 256, 1);

    // ---- head ----
    hreduce1_kernel<<<dim3(32, Bq), 256>>>();
    hreduce2_kernel<<<Bq, 256>>>();
    cls1_kernel<<<1, 256>>>(cw1, cg, cb);
    cls2_kernel<<<1, 192>>>(cw2, out);
}

// round 12
// speedup vs baseline: 1.0856x; 1.0856x over previous
#include <cuda_runtime.h>
#include <cuda_bf16.h>
#include <math_constants.h>
#include <cstdint>

// Problem constants
#define Bq   4
#define Nq   4096
#define Kq   9
#define BNT  16384           // B*N
#define CNT_EDGE 147456.0f   // B*N*K
#define STG  3               // cp.async pipeline stages (k32 each)
#define STGB 40960           // bytes/stage: 4 planes x 128 rows x 80B

// ------------------------- scratch (device globals; no allocs) -------------
__device__ float g_ab[(size_t)BNT * 512];     // GEMM out [A | Bm]
__device__ int   g_idx[BNT * Kq];
__device__ float g_wc[256 * 512];             // f32 weights (decoder gemm_sm)
__device__ float g_ymax[(size_t)BNT * 256];
__device__ float g_ymin[(size_t)BNT * 256];
__device__ float g_act1[(size_t)BNT * 64];    // out1 f32 (decoder input)
__device__ float g_low[(size_t)BNT * 48];
__device__ float g_fused[(size_t)BNT * 256];
__device__ float g_stats[1024];
__device__ float g_h[Bq * 512];
__device__ float g_h2[Bq * 256];
__device__ float g_hpart[2][Bq][32][256];
// bf16 split planes (hi/lo): activations row-major [m][Kp], Kp mult of 32
__device__ __nv_bfloat16 g_ph[(size_t)BNT * 256];
__device__ __nv_bfloat16 g_pl[(size_t)BNT * 256];
__device__ __nv_bfloat16 g_lowh[(size_t)BNT * 64];
__device__ __nv_bfloat16 g_lowl[(size_t)BNT * 64];
// weights n-major [n][Kp]
__device__ __nv_bfloat16 g_wbh[512 * 256];
__device__ __nv_bfloat16 g_wbl[512 * 256];

// ------------------------- helpers -----------------------------------------
__device__ __forceinline__ uint32_t sptr(const void* p)
{
    return (uint32_t)__cvta_generic_to_shared(p);
}

#define CPA16(dst, src) \
    asm volatile("cp.async.cg.shared.global [%0], [%1], 16;" \
                 :: "r"(dst), "l"(src) : "memory")
#define CPA_COMMIT() asm volatile("cp.async.commit_group;" ::: "memory")
#define CPA_WAIT1()  asm volatile("cp.async.wait_group 1;" ::: "memory")
#define LDSM4(r0, r1, r2, r3, addr) \
    asm volatile("ldmatrix.sync.aligned.m8n8.x4.shared.b16 {%0,%1,%2,%3}, [%4];" \
                 : "=r"(r0), "=r"(r1), "=r"(r2), "=r"(r3) : "r"(addr))
#define MMA4(CC, AA, B0, B1) \
    asm volatile("mma.sync.aligned.m16n8k16.row.col.f32.bf16.bf16.f32 " \
                 "{%0,%1,%2,%3}, {%4,%5,%6,%7}, {%8,%9}, {%0,%1,%2,%3};" \
                 : "+f"(CC[0]), "+f"(CC[1]), "+f"(CC[2]), "+f"(CC[3]) \
                 : "r"(AA[0]), "r"(AA[1]), "r"(AA[2]), "r"(AA[3]), \
                   "r"(B0), "r"(B1))

__device__ __forceinline__ void bf16_split(float v, __nv_bfloat16& h,
                                           __nv_bfloat16& l)
{
    h = __float2bfloat16(v);
    l = __float2bfloat16(v - __bfloat162float(h));
}

// ------------------------- transpose x -> bf16 planes (Kp=32) --------------
__global__ void transpose_kernel(const float* __restrict__ x)
{
    int i = blockIdx.x * blockDim.x + threadIdx.x;
    if (i < BNT * 32) {
        int k  = i & 31;
        int bn = i >> 5;
        int b  = bn >> 12;
        int n  = bn & (Nq - 1);
        float v = (k < 3) ? x[((size_t)b * 3 + k) * Nq + n] : 0.f;
        __nv_bfloat16 h, l;
        bf16_split(v, h, l);
        g_ph[i] = h; g_pl[i] = l;
    }
}

// ------------------------- KNN: top-9, split-m with merge ------------------
__global__ __launch_bounds__(256) void knn_kernel(const float* __restrict__ x)
{
    __shared__ float sx0[Nq];
    __shared__ float sx1[Nq];
    __shared__ float sx2[Nq];
    int tid = threadIdx.x;
    int b = blockIdx.x >> 5;
    int rowBase = (blockIdx.x & 31) * 128;
    const float* xb = x + (size_t)b * 3 * Nq;
    for (int t = tid; t < Nq; t += 256) {
        sx0[t] = xb[t];
        sx1[t] = xb[Nq + t];
        sx2[t] = xb[2 * Nq + t];
    }
    __syncthreads();

    int half = tid >> 7;
    int pt   = tid & 127;
    int n = rowBase + pt;
    float a0 = sx0[n], a1 = sx1[n], a2 = sx2[n];
    float an = a0 * a0 + a1 * a1 + a2 * a2;

    float bd[9]; int bi[9];
    #pragma unroll
    for (int j = 0; j < 9; j++) { bd[j] = CUDART_INF_F; bi[j] = 0; }

    int mS = half * 2048, mE = mS + 2048;
    for (int m = mS; m < mE; m++) {
        float c0 = sx0[m], c1 = sx1[m], c2 = sx2[m];
        float cn = c0 * c0 + c1 * c1 + c2 * c2;
        float dt = a0 * c0 + a1 * c1 + a2 * c2;
        float d  = an + cn - 2.f * dt;
        if (m == n) d = CUDART_INF_F;
        if (d < bd[8]) {
            bd[8] = d; bi[8] = m;
            #pragma unroll
            for (int j = 8; j > 0; --j) {
                if (bd[j] < bd[j - 1]) {
                    float td = bd[j]; bd[j] = bd[j - 1]; bd[j - 1] = td;
                    int   ti = bi[j]; bi[j] = bi[j - 1]; bi[j - 1] = ti;
                }
            }
        }
    }
    __syncthreads();
    float* cd = sx0;
    int*   ci = (int*)sx1;
    if (half) {
        #pragma unroll
        for (int j = 0; j < 9; j++) { cd[pt * 9 + j] = bd[j]; ci[pt * 9 + j] = bi[j]; }
    }
    __syncthreads();
    if (!half) {
        #pragma unroll
        for (int j = 0; j < 9; j++) {
            float d = cd[pt * 9 + j]; int im = ci[pt * 9 + j];
            if (d < bd[8]) {
                bd[8] = d; bi[8] = im;
                #pragma unroll
                for (int jj = 8; jj > 0; --jj) {
                    if (bd[jj] < bd[jj - 1]) {
                        float td = bd[jj]; bd[jj] = bd[jj - 1]; bd[jj - 1] = td;
                        int   ti = bi[jj]; bi[jj] = bi[jj - 1]; bi[jj - 1] = ti;
                    }
                }
            }
        }
        int* op = g_idx + ((size_t)b * Nq + n) * Kq;
        #pragma unroll
        for (int j = 0; j < 9; j++) op[j] = bi[j];
    }
}

// ------------------------- weight prep (bf16 n-major planes) ---------------
__global__ void prep_edge_wb(const float* __restrict__ W, int Cin, int Cout,
                             int Kp)
{
    int i = blockIdx.x * blockDim.x + threadIdx.x;
    if (i < 2 * Cout * Kp) {
        int n = i / Kp, c = i % Kp;
        float v = 0.f;
        if (c < Cin)
            v = (n < Cout)
              ? W[(size_t)n * 2 * Cin + c] - W[(size_t)n * 2 * Cin + Cin + c]
              : W[(size_t)(n - Cout) * 2 * Cin + Cin + c];
        __nv_bfloat16 h, l;
        bf16_split(v, h, l);
        g_wbh[i] = h; g_wbl[i] = l;
    }
}

__global__ void prep_plain_wb(const float* __restrict__ W, int Cin, int Cout,
                              int rowStride, int colOff, int Kp)
{
    int i = blockIdx.x * blockDim.x + threadIdx.x;
    if (i < Cout * Kp) {
        int n = i / Kp, c = i % Kp;
        float v = (c < Cin) ? W[(size_t)n * rowStride + colOff + c] : 0.f;
        __nv_bfloat16 h, l;
        bf16_split(v, h, l);
        g_wbh[i] = h; g_wbl[i] = l;
    }
}

__global__ void prep_plain_w(const float* __restrict__ W, int Cin, int Cout,
                             int rowStride, int colOff)
{
    int i = blockIdx.x * blockDim.x + threadIdx.x;
    if (i < Cin * Cout) {
        int c = i / Cout, o = i % Cout;
        g_wc[(size_t)c * Cout + o] = W[(size_t)o * rowStride + colOff + c];
    }
}

// ------------------------- cp.async 3-stage k32 split-bf16 GEMM ------------
// C(M,N) = A(M,Kp) * B(Kp,N);  A planes row-major, B planes n-major.
// 3 terms: Ah*Bh + Al*Bh + Ah*Bl.  Block 128x128, 8 warps (4m x 2n),
// warp tile 32x64.  Stage = k32 (2 k16 sub-steps per sync).  Row pitch 80B.
__global__ __launch_bounds__(256) void gemm_async(
    const __nv_bfloat16* __restrict__ Ah,
    const __nv_bfloat16* __restrict__ Al,
    float* __restrict__ C, int Kp, int N, int acc)
{
    extern __shared__ __nv_bfloat16 dsm[];
    uint32_t sm0 = sptr(dsm);

    int tid = threadIdx.x, lane = tid & 31, wid = tid >> 5;
    int warp_m = wid & 3, warp_n = wid >> 2;
    int m0 = blockIdx.y * 128, n0 = blockIdx.x * 128;
    int g = lane >> 2, t4 = lane & 3;

    float c[2][8][4];
    #pragma unroll
    for (int i = 0; i < 2; i++)
        #pragma unroll
        for (int j = 0; j < 8; j++)
            #pragma unroll
            for (int r = 0; r < 4; r++) c[i][j][r] = 0.f;

    int nch = Kp >> 5;           // k32 chunks

    int lrow = lane & 15, khalf = (lane >> 4) * 16;
    uint32_t aoff[2], boff[4];
    #pragma unroll
    for (int i = 0; i < 2; i++)
        aoff[i] = (warp_m * 32 + i * 16 + lrow) * 80 + khalf;
    #pragma unroll
    for (int q = 0; q < 4; q++)
        boff[q] = (warp_n * 64 + q * 16 + lrow) * 80 + khalf;

    // fill: 2048 items (4 planes x 128 rows x 4 16B-subs), 8 per thread
    auto fill_stage = [&](int s, int ch) {
        int k0 = ch * 32;
        #pragma unroll
        for (int t = 0; t < 8; t++) {
            int it = tid + t * 256;
            int c4 = it & 3, row = (it >> 2) & 127, pln = it >> 9;
            const __nv_bfloat16* src;
            if (pln == 0)      src = Ah    + (size_t)(m0 + row) * Kp + k0 + c4 * 8;
            else if (pln == 1) src = Al    + (size_t)(m0 + row) * Kp + k0 + c4 * 8;
            else if (pln == 2) src = g_wbh + (size_t)(n0 + row) * Kp + k0 + c4 * 8;
            else               src = g_wbl + (size_t)(n0 + row) * Kp + k0 + c4 * 8;
            CPA16(sm0 + s * STGB + pln * 10240 + row * 80 + c4 * 16, src);
        }
        CPA_COMMIT();
    };

    #pragma unroll
    for (int s = 0; s < STG - 1; s++) {
        if (s < nch) fill_stage(s, s);
        else CPA_COMMIT();
    }

    for (int ch = 0; ch < nch; ch++) {
        int s = ch % STG;
        CPA_WAIT1();
        __syncthreads();
        int pre = ch + STG - 1;
        if (pre < nch) fill_stage(pre % STG, pre);
        else CPA_COMMIT();

        uint32_t sAs = sm0 + s * STGB, sBs = sAs + 20480;
        #pragma unroll
        for (int ks = 0; ks < 2; ks++) {
            uint32_t ko = ks * 32;
            uint32_t ah[2][4], al[2][4];
            #pragma unroll
            for (int i = 0; i < 2; i++) {
                LDSM4(ah[i][0], ah[i][1], ah[i][2], ah[i][3], sAs + aoff[i] + ko);
                LDSM4(al[i][0], al[i][1], al[i][2], al[i][3],
                      sAs + 10240 + aoff[i] + ko);
            }
            #pragma unroll
            for (int q = 0; q < 4; q++) {
                uint32_t bh0, bh1, bh2, bh3, bl0, bl1, bl2, bl3;
                LDSM4(bh0, bh1, bh2, bh3, sBs + boff[q] + ko);
                LDSM4(bl0, bl1, bl2, bl3, sBs + 10240 + boff[q] + ko);
                int j0 = q * 2, j1 = q * 2 + 1;
                MMA4(c[0][j0], ah[0], bh0, bh2);
                MMA4(c[0][j0], al[0], bh0, bh2);
                MMA4(c[0][j0], ah[0], bl0, bl2);
                MMA4(c[1][j0], ah[1], bh0, bh2);
                MMA4(c[1][j0], al[1], bh0, bh2);
                MMA4(c[1][j0], ah[1], bl0, bl2);
                MMA4(c[0][j1], ah[0], bh1, bh3);
                MMA4(c[0][j1], al[0], bh1, bh3);
                MMA4(c[0][j1], ah[0], bl1, bl3);
                MMA4(c[1][j1], ah[1], bh1, bh3);
                MMA4(c[1][j1], al[1], bh1, bh3);
                MMA4(c[1][j1], ah[1], bl1, bl3);
            }
        }
    }

    #pragma unroll
    for (int i = 0; i < 2; i++) {
        int m = m0 + warp_m * 32 + i * 16 + g;
        #pragma unroll
        for (int j = 0; j < 8; j++) {
            int n = n0 + warp_n * 64 + j * 8 + t4 * 2;
            float2* p0 = (float2*)&C[(size_t)m * N + n];
            float2* p1 = (float2*)&C[(size_t)(m + 8) * N + n];
            if (acc) {
                float2 v0 = *p0, v1 = *p1;
                v0.x += c[i][j][0]; v0.y += c[i][j][1];
                v1.x += c[i][j][2]; v1.y += c[i][j][3];
                *p0 = v0; *p1 = v1;
            } else {
                *p0 = make_float2(c[i][j][0], c[i][j][1]);
                *p1 = make_float2(c[i][j][2], c[i][j][3]);
            }
        }
    }
}

// ------------------------- small FFMA GEMM (decoder, N=48) -----------------
__global__ __launch_bounds__(256) void gemm_sm(const float* __restrict__ X,
                                               float* __restrict__ C,
                                               int K, int N)
{
    __shared__ float sX[16][65];
    __shared__ float sW[16][64];
    int tx = threadIdx.x, ty = threadIdx.y;
    int tid = ty * 16 + tx;
    int m0 = blockIdx.y * 64;
    int n0 = blockIdx.x * 64;

    float accum[4][4];
    #pragma unroll
    for (int i = 0; i < 4; i++)
        #pragma unroll
        for (int j = 0; j < 4; j++) accum[i][j] = 0.f;

    for (int k0 = 0; k0 < K; k0 += 16) {
        for (int t = tid; t < 64 * 16; t += 256) {
            int m = t >> 4, k = t & 15;
            sX[k][m] = (k0 + k < K) ? X[(size_t)(m0 + m) * K + k0 + k] : 0.f;
        }
        for (int t = tid; t < 16 * 64; t += 256) {
            int k = t >> 6, n = t & 63;
            sW[k][n] = (k0 + k < K && n0 + n < N)
                     ? g_wc[(size_t)(k0 + k) * N + n0 + n] : 0.f;
        }
        __syncthreads();
        #pragma unroll
        for (int kk = 0; kk < 16; kk++) {
            float xr[4], wr[4];
            #pragma unroll
            for (int i = 0; i < 4; i++) xr[i] = sX[kk][ty * 4 + i];
            #pragma unroll
            for (int j = 0; j < 4; j++) wr[j] = sW[kk][tx * 4 + j];
            #pragma unroll
            for (int i = 0; i < 4; i++)
                #pragma unroll
                for (int j = 0; j < 4; j++)
                    accum[i][j] = fmaf(xr[i], wr[j], accum[i][j]);
        }
        __syncthreads();
    }
    #pragma unroll
    for (int i = 0; i < 4; i++) {
        int m = m0 + ty * 4 + i;
        #pragma unroll
        for (int j = 0; j < 4; j++) {
            int n = n0 + tx * 4 + j;
            if (n < N) C[(size_t)m * N + n] = accum[i][j];
        }
    }
}

// ------------------------- gather-max/min + BN stats -----------------------
#define GN 16
__global__ void gather_kernel(int Cout)
{
    __shared__ int sidx[GN * Kq];
    int n0 = blockIdx.x * GN;
    for (int t = threadIdx.x; t < GN * Kq; t += blockDim.x)
        sidx[t] = g_idx[(size_t)n0 * Kq + t];
    __syncthreads();

    int o  = threadIdx.x;
    int C2 = 2 * Cout;
    float lsum = 0.f, lssq = 0.f;
    for (int g = 0; g < GN; g++) {
        int bn = n0 + g;
        int bbase = (bn >> 12) << 12;
        float a = g_ab[(size_t)bn * C2 + o];
        float mx = -CUDART_INF_F, mn = CUDART_INF_F, s = 0.f, sq = 0.f;
        #pragma unroll
        for (int k = 0; k < Kq; k++) {
            int j = sidx[g * Kq + k];
            float v = g_ab[(size_t)(bbase + j) * C2 + Cout + o];
            mx = fmaxf(mx, v); mn = fminf(mn, v);
            s += v; sq = fmaf(v, v, sq);
        }
        g_ymax[(size_t)bn * Cout + o] = a + mx;
        g_ymin[(size_t)bn * Cout + o] = a + mn;
        lsum += fmaf((float)Kq, a, s);
        lssq += (float)Kq * a * a + 2.f * a * s + sq;
    }
    atomicAdd(&g_stats[o], lsum);
    atomicAdd(&g_stats[512 + o], lssq);
}

// ------------------------- column stats (decoder BN) -----------------------
__global__ void colstats_kernel(const float* __restrict__ Y, int C, int Mrows)
{
    __shared__ float ss[256];
    __shared__ float sq[256];
    int o = blockIdx.x;
    float s = 0.f, q = 0.f;
    for (int m = threadIdx.x; m < Mrows; m += 256) {
        float v = Y[(size_t)m * C + o];
        s += v; q = fmaf(v, v, q);
    }
    ss[threadIdx.x] = s; sq[threadIdx.x] = q;
    __syncthreads();
    for (int st = 128; st; st >>= 1) {
        if (threadIdx.x < st) {
            ss[threadIdx.x] += ss[threadIdx.x + st];
            sq[threadIdx.x] += sq[threadIdx.x + st];
        }
        __syncthreads();
    }
    if (threadIdx.x == 0) { g_stats[o] = ss[0]; g_stats[512 + o] = sq[0]; }
}

// ---------- BN + ReLU (+ max-select) + plane split (PS = padded K) ---------
__global__ void bnrelu_kernel(const float* __restrict__ ymax,
                              const float* __restrict__ ymin,
                              const float* __restrict__ gg,
                              const float* __restrict__ bb,
                              float* __restrict__ outp,
                              __nv_bfloat16* __restrict__ ph,
                              __nv_bfloat16* __restrict__ pl,
                              int C, int PS, float invCnt, int totalPS)
{
    for (int i = blockIdx.x * blockDim.x + threadIdx.x; i < totalPS;
         i += gridDim.x * blockDim.x) {
        int o = i % PS, row = i / PS;
        if (o < C) {
            int j = row * C + o;
            float mean = g_stats[o] * invCnt;
            float var  = fmaf(-mean, mean, g_stats[512 + o] * invCnt);
            float sc   = gg[o] * rsqrtf(var + 1e-5f);
            float sh   = fmaf(-mean, sc, bb[o]);
            float y    = (sc >= 0.f) ? ymax[j] : ymin[j];
            float r    = fmaxf(fmaf(sc, y, sh), 0.f);
            if (outp) outp[j] = r;
            __nv_bfloat16 h, l;
            bf16_split(r, h, l);
            ph[i] = h; pl[i] = l;
        } else {
            ph[i] = __float2bfloat16(0.f);
            pl[i] = __float2bfloat16(0.f);
        }
    }
}

// ------------------------- global max/mean pool (2-stage) ------------------
__global__ void hreduce1_kernel()
{
    int b = blockIdx.y, chunk = blockIdx.x, o = threadIdx.x;
    const float* f = g_fused + ((size_t)b * Nq + chunk * 128) * 256 + o;
    float mx = -CUDART_INF_F, s = 0.f;
    for (int n = 0; n < 128; n++) {
        float v = f[(size_t)n * 256];
        mx = fmaxf(mx, v); s += v;
    }
    g_hpart[0][b][chunk][o] = mx;
    g_hpart[1][b][chunk][o] = s;
}

__global__ void hreduce2_kernel()
{
    int b = blockIdx.x, o = threadIdx.x;
    float mx = -CUDART_INF_F, s = 0.f;
    #pragma unroll
    for (int c = 0; c < 32; c++) {
        mx = fmaxf(mx, g_hpart[0][b][c][o]);
        s += g_hpart[1][b][c][o];
    }
    g_h[b * 512 + o]       = mx;
    g_h[b * 512 + 256 + o] = s * (1.f / Nq);
}

// ------------------------- classifier head ---------------------------------
__global__ void cls1_kernel(const float* __restrict__ W,
                            const float* __restrict__ gg,
                            const float* __restrict__ bb)
{
    int o = threadIdx.x;
    float y[4];
    #pragma unroll
    for (int b = 0; b < 4; b++) {
        float s = 0.f;
        const float* wr = W + (size_t)o * 512;
        const float* hr = g_h + b * 512;
        for (int c = 0; c < 512; c++) s = fmaf(wr[c], hr[c], s);
        y[b] = s;
    }
    float mean = 0.25f * (y[0] + y[1] + y[2] + y[3]);
    float ssq  = y[0]*y[0] + y[1]*y[1] + y[2]*y[2] + y[3]*y[3];
    float var  = fmaf(-mean, mean, 0.25f * ssq);
    float sc   = gg[o] * rsqrtf(var + 1e-5f);
    float sh   = fmaf(-mean, sc, bb[o]);
    #pragma unroll
    for (int b = 0; b < 4; b++)
        g_h2[b * 256 + o] = fmaxf(fmaf(sc, y[b], sh), 0.f);
}

__global__ void cls2_kernel(const float* __restrict__ W, float* __restrict__ out)
{
    int t = threadIdx.x;
    if (t < 160) {
        int b = t / 40, o = t % 40;
        float s = 0.f;
        for (int c = 0; c < 256; c++)
            s = fmaf(W[(size_t)o * 256 + c], g_h2[b * 256 + c], s);
        out[b * 40 + o] = s;
    }
}

// ------------------------- host launch sequence ----------------------------
extern "C" void kernel_launch(void* const* d_in, const int* in_sizes, int n_in,
                              void* d_out, int out_size)
{
    const float* x     = (const float*)d_in[0];
    const float* w1    = (const float*)d_in[2];
    const float* g1    = (const float*)d_in[3];
    const float* b1    = (const float*)d_in[4];
    const float* w2    = (const float*)d_in[5];
    const float* g2    = (const float*)d_in[6];
    const float* b2    = (const float*)d_in[7];
    const float* w3    = (const float*)d_in[8];
    const float* g3    = (const float*)d_in[9];
    const float* b3    = (const float*)d_in[10];
    const float* w4    = (const float*)d_in[11];
    const float* g4    = (const float*)d_in[12];
    const float* b4    = (const float*)d_in[13];
    const float* dec_w = (const float*)d_in[14];
    const float* dec_g = (const float*)d_in[15];
    const float* dec_b = (const float*)d_in[16];
    const float* fus_w = (const float*)d_in[17];
    const float* cw1   = (const float*)d_in[18];
    const float* cg    = (const float*)d_in[19];
    const float* cb    = (const float*)d_in[20];
    const float* cw2   = (const float*)d_in[21];
    float* out = (float*)d_out;

    static int smem_set = 0;
    if (!smem_set) {
        cudaFuncSetAttribute(gemm_async,
            cudaFuncAttributeMaxDynamicSharedMemorySize, STG * STGB);
        smem_set = 1;
    }
    const int GSM = STG * STGB;   // 122880 B dynamic smem

    void *p_ab, *p_ymax, *p_ymin, *p_act1, *p_low, *p_fused, *p_stats,
         *p_ph, *p_pl, *p_lowh, *p_lowl;
    cudaGetSymbolAddress(&p_ab,    g_ab);
    cudaGetSymbolAddress(&p_ymax,  g_ymax);
    cudaGetSymbolAddress(&p_ymin,  g_ymin);
    cudaGetSymbolAddress(&p_act1,  g_act1);
    cudaGetSymbolAddress(&p_low,   g_low);
    cudaGetSymbolAddress(&p_fused, g_fused);
    cudaGetSymbolAddress(&p_stats, g_stats);
    cudaGetSymbolAddress(&p_ph,    g_ph);
    cudaGetSymbolAddress(&p_pl,    g_pl);
    cudaGetSymbolAddress(&p_lowh,  g_lowh);
    cudaGetSymbolAddress(&p_lowl,  g_lowl);

    const __nv_bfloat16* ph = (const __nv_bfloat16*)p_ph;
    const __nv_bfloat16* pl = (const __nv_bfloat16*)p_pl;
    const float invEdge = 1.f / CNT_EDGE;
    const dim3 tb16(16, 16);

    transpose_kernel<<<(BNT * 32 + 255) / 256, 256>>>(x);
    knn_kernel<<<128, 256>>>(x);

    // ---- EdgeConv 1: Cin=3 (Kp=32), Cout=64 (N=128) ----
    prep_edge_wb<<<(128 * 32 + 255) / 256, 256>>>(w1, 3, 64, 32);
    gemm_async<<<dim3(1, 128), 256, GSM>>>(ph, pl, (float*)p_ab, 32, 128, 0);
    cudaMemsetAsync(p_stats, 0, 1024 * sizeof(float));
    gather_kernel<<<BNT / GN, 64>>>(64);
    bnrelu_kernel<<<(BNT * 64 + 255) / 256, 256>>>((const float*)p_ymax,
        (const float*)p_ymin, g1, b1, (float*)p_act1,
        (__nv_bfloat16*)p_ph, (__nv_bfloat16*)p_pl, 64, 64, invEdge, BNT * 64);

    // ---- EdgeConv 2: Kp=64, Cout=128 (N=256) ----
    prep_edge_wb<<<(256 * 64 + 255) / 256, 256>>>(w2, 64, 128, 64);
    gemm_async<<<dim3(2, 128), 256, GSM>>>(ph, pl, (float*)p_ab, 64, 256, 0);
    cudaMemsetAsync(p_stats, 0, 1024 * sizeof(float));
    gather_kernel<<<BNT / GN, 128>>>(128);
    bnrelu_kernel<<<(BNT * 128 + 255) / 256, 256>>>((const float*)p_ymax,
        (const float*)p_ymin, g2, b2, nullptr,
        (__nv_bfloat16*)p_ph, (__nv_bfloat16*)p_pl, 128, 128, invEdge, BNT * 128);

    // ---- EdgeConv 3: Kp=128, Cout=256 (N=512) ----
    prep_edge_wb<<<(512 * 128 + 255) / 256, 256>>>(w3, 128, 256, 128);
    gemm_async<<<dim3(4, 128), 256, GSM>>>(ph, pl, (float*)p_ab, 128, 512, 0);
    cudaMemsetAsync(p_stats, 0, 1024 * sizeof(float));
    gather_kernel<<<BNT / GN, 256>>>(256);
    bnrelu_kernel<<<(BNT * 256 + 255) / 256, 256>>>((const float*)p_ymax,
        (const float*)p_ymin, g3, b3, nullptr,
        (__nv_bfloat16*)p_ph, (__nv_bfloat16*)p_pl, 256, 256, invEdge, BNT * 256);

    // ---- EdgeConv 4: Kp=256, Cout=256 (N=512) ----
    prep_edge_wb<<<(512 * 256 + 255) / 256, 256>>>(w4, 256, 256, 256);
    gemm_async<<<dim3(4, 128), 256, GSM>>>(ph, pl, (float*)p_ab, 256, 512, 0);
    cudaMemsetAsync(p_stats, 0, 1024 * sizeof(float));
    gather_kernel<<<BNT / GN, 256>>>(256);
    bnrelu_kernel<<<(BNT * 256 + 255) / 256, 256>>>((const float*)p_ymax,
        (const float*)p_ymin, g4, b4, nullptr,
        (__nv_bfloat16*)p_ph, (__nv_bfloat16*)p_pl, 256, 256, invEdge, BNT * 256);
    // g_ph/g_pl now hold out4 planes (Kp=256)

    // ---- decoder: low = relu(bn(dec_w @ out1)) ----
    prep_plain_w<<<(64 * 48 + 255) / 256, 256>>>(dec_w, 64, 48, 64, 0);
    gemm_sm<<<dim3(1, 256), tb16>>>((const float*)p_act1, (float*)p_low, 64, 48);
    colstats_kernel<<<48, 256>>>((const float*)p_low, 48, BNT);
    bnrelu_kernel<<<(BNT * 64 + 255) / 256, 256>>>((const float*)p_low,
        (const float*)p_low, dec_g, dec_b, nullptr,
        (__nv_bfloat16*)p_lowh, (__nv_bfloat16*)p_lowl, 48, 64, 1.f / BNT,
        BNT * 64);

    // ---- fusion: fused = fus_w @ concat([out4, low]) ----
    prep_plain_wb<<<(256 * 256 + 255) / 256, 256>>>(fus_w, 256, 256, 304, 0, 256);
    gemm_async<<<dim3(2, 128), 256, GSM>>>(ph, pl, (float*)p_fused, 256, 256, 0);
    prep_plain_wb<<<(256 * 64 + 255) / 256, 256>>>(fus_w, 48, 256, 304, 256, 64);
    gemm_async<<<dim3(2, 128), 256, GSM>>>((const __nv_bfloat16*)p_lowh,
        (const __nv_bfloat16*)p_lowl, (float*)p_fused, 64, 256, 1);

    // ---- head ----
    hreduce1_kernel<<<dim3(32, Bq), 256>>>();
    hreduce2_kernel<<<Bq, 256>>>();
    cls1_kernel<<<1, 256>>>(cw1, cg, cb);
    cls2_kernel<<<1, 192>>>(cw2, out);
}

// round 14
// speedup vs baseline: 1.1408x; 1.0509x over previous
#include <cuda_runtime.h>
#include <cuda_bf16.h>
#include <math_constants.h>
#include <cstdint>

// Problem constants
#define Bq   4
#define Nq   4096
#define Kq   9
#define BNT  16384           // B*N
#define CNT_EDGE 147456.0f   // B*N*K
#define STG  3               // cp.async pipeline stages

// ------------------------- scratch (device globals; no allocs) -------------
__device__ float g_ab[(size_t)BNT * 512];     // GEMM out [A | Bm]
__device__ int   g_idx[BNT * Kq];
__device__ float g_wc[256 * 512];             // f32 weights (decoder gemm_sm)
__device__ float g_ysel[(size_t)BNT * 256];   // gather output (sign-selected)
__device__ float g_act1[(size_t)BNT * 64];    // out1 f32 (decoder input)
__device__ float g_low[(size_t)BNT * 48];
__device__ float g_fused[(size_t)BNT * 256];
__device__ float g_stats[1024];
__device__ float g_stats2[1024];              // decoder stats
__device__ float g_h[Bq * 512];
__device__ float g_h2[Bq * 256];
__device__ float g_hpart[2][Bq][32][256];
// bf16 split planes (hi/lo): activations row-major [m][Kp], Kp mult of 16
__device__ __nv_bfloat16 g_ph[(size_t)BNT * 256];
__device__ __nv_bfloat16 g_pl[(size_t)BNT * 256];
__device__ __nv_bfloat16 g_lowh[(size_t)BNT * 48];
__device__ __nv_bfloat16 g_lowl[(size_t)BNT * 48];
// weights n-major [n][Kp]
__device__ __nv_bfloat16 g_wbh[512 * 256];
__device__ __nv_bfloat16 g_wbl[512 * 256];

// ------------------------- helpers -----------------------------------------
__device__ __forceinline__ uint32_t sptr(const void* p)
{
    return (uint32_t)__cvta_generic_to_shared(p);
}

#define CPA16(dst, src) \
    asm volatile("cp.async.cg.shared.global [%0], [%1], 16;" \
                 :: "r"(dst), "l"(src) : "memory")
#define CPA_COMMIT() asm volatile("cp.async.commit_group;" ::: "memory")
#define CPA_WAIT1()  asm volatile("cp.async.wait_group 1;" ::: "memory")
#define LDSM4(r0, r1, r2, r3, addr) \
    asm volatile("ldmatrix.sync.aligned.m8n8.x4.shared.b16 {%0,%1,%2,%3}, [%4];" \
                 : "=r"(r0), "=r"(r1), "=r"(r2), "=r"(r3) : "r"(addr))
#define MMA4(CC, AA, B0, B1) \
    asm volatile("mma.sync.aligned.m16n8k16.row.col.f32.bf16.bf16.f32 " \
                 "{%0,%1,%2,%3}, {%4,%5,%6,%7}, {%8,%9}, {%0,%1,%2,%3};" \
                 : "+f"(CC[0]), "+f"(CC[1]), "+f"(CC[2]), "+f"(CC[3]) \
                 : "r"(AA[0]), "r"(AA[1]), "r"(AA[2]), "r"(AA[3]), \
                   "r"(B0), "r"(B1))

__device__ __forceinline__ void bf16_split(float v, __nv_bfloat16& h,
                                           __nv_bfloat16& l)
{
    h = __float2bfloat16(v);
    l = __float2bfloat16(v - __bfloat162float(h));
}

// ------------------------- transpose x -> bf16 planes (Kp=16) --------------
__global__ void transpose_kernel(const float* __restrict__ x)
{
    int i = blockIdx.x * blockDim.x + threadIdx.x;
    if (i < BNT * 16) {
        int k  = i & 15;
        int bn = i >> 4;
        int b  = bn >> 12;
        int n  = bn & (Nq - 1);
        float v = (k < 3) ? x[((size_t)b * 3 + k) * Nq + n] : 0.f;
        __nv_bfloat16 h, l;
        bf16_split(v, h, l);
        g_ph[i] = h; g_pl[i] = l;
    }
}

// ------------------------- KNN: top-9, split-m with merge ------------------
__global__ __launch_bounds__(256) void knn_kernel(const float* __restrict__ x)
{
    __shared__ float sx0[Nq];
    __shared__ float sx1[Nq];
    __shared__ float sx2[Nq];
    int tid = threadIdx.x;
    int b = blockIdx.x >> 5;
    int rowBase = (blockIdx.x & 31) * 128;
    const float* xb = x + (size_t)b * 3 * Nq;
    for (int t = tid; t < Nq; t += 256) {
        sx0[t] = xb[t];
        sx1[t] = xb[Nq + t];
        sx2[t] = xb[2 * Nq + t];
    }
    __syncthreads();

    int half = tid >> 7;
    int pt   = tid & 127;
    int n = rowBase + pt;
    float a0 = sx0[n], a1 = sx1[n], a2 = sx2[n];
    float an = a0 * a0 + a1 * a1 + a2 * a2;

    float bd[9]; int bi[9];
    #pragma unroll
    for (int j = 0; j < 9; j++) { bd[j] = CUDART_INF_F; bi[j] = 0; }

    int mS = half * 2048, mE = mS + 2048;
    for (int m = mS; m < mE; m++) {
        float c0 = sx0[m], c1 = sx1[m], c2 = sx2[m];
        float cn = c0 * c0 + c1 * c1 + c2 * c2;
        float dt = a0 * c0 + a1 * c1 + a2 * c2;
        float d  = an + cn - 2.f * dt;
        if (m == n) d = CUDART_INF_F;
        if (d < bd[8]) {
            bd[8] = d; bi[8] = m;
            #pragma unroll
            for (int j = 8; j > 0; --j) {
                if (bd[j] < bd[j - 1]) {
                    float td = bd[j]; bd[j] = bd[j - 1]; bd[j - 1] = td;
                    int   ti = bi[j]; bi[j] = bi[j - 1]; bi[j - 1] = ti;
                }
            }
        }
    }
    __syncthreads();
    float* cd = sx0;
    int*   ci = (int*)sx1;
    if (half) {
        #pragma unroll
        for (int j = 0; j < 9; j++) { cd[pt * 9 + j] = bd[j]; ci[pt * 9 + j] = bi[j]; }
    }
    __syncthreads();
    if (!half) {
        #pragma unroll
        for (int j = 0; j < 9; j++) {
            float d = cd[pt * 9 + j]; int im = ci[pt * 9 + j];
            if (d < bd[8]) {
                bd[8] = d; bi[8] = im;
                #pragma unroll
                for (int jj = 8; jj > 0; --jj) {
                    if (bd[jj] < bd[jj - 1]) {
                        float td = bd[jj]; bd[jj] = bd[jj - 1]; bd[jj - 1] = td;
                        int   ti = bi[jj]; bi[jj] = bi[jj - 1]; bi[jj - 1] = ti;
                    }
                }
            }
        }
        int* op = g_idx + ((size_t)b * Nq + n) * Kq;
        #pragma unroll
        for (int j = 0; j < 9; j++) op[j] = bi[j];
    }
}

// ------------------------- weight prep (bf16 n-major planes) ---------------
// Also zeroes g_stats (runs after prior layer's bnrelu, before this gather).
__global__ void prep_edge_wb(const float* __restrict__ W, int Cin, int Cout,
                             int Kp)
{
    int i = blockIdx.x * blockDim.x + threadIdx.x;
    if (i < 1024) g_stats[i] = 0.f;
    if (i < 2 * Cout * Kp) {
        int n = i / Kp, c = i % Kp;
        float v = 0.f;
        if (c < Cin)
            v = (n < Cout)
              ? W[(size_t)n * 2 * Cin + c] - W[(size_t)n * 2 * Cin + Cin + c]
              : W[(size_t)(n - Cout) * 2 * Cin + Cin + c];
        __nv_bfloat16 h, l;
        bf16_split(v, h, l);
        g_wbh[i] = h; g_wbl[i] = l;
    }
}

__global__ void prep_plain_wb(const float* __restrict__ W, int Cin, int Cout,
                              int rowStride, int colOff, int Kp)
{
    int i = blockIdx.x * blockDim.x + threadIdx.x;
    if (i < Cout * Kp) {
        int n = i / Kp, c = i % Kp;
        float v = (c < Cin) ? W[(size_t)n * rowStride + colOff + c] : 0.f;
        __nv_bfloat16 h, l;
        bf16_split(v, h, l);
        g_wbh[i] = h; g_wbl[i] = l;
    }
}

__global__ void prep_plain_w(const float* __restrict__ W, int Cin, int Cout,
                             int rowStride, int colOff)
{
    int i = blockIdx.x * blockDim.x + threadIdx.x;
    if (i < Cin * Cout) {
        int c = i / Cout, o = i % Cout;
        g_wc[(size_t)c * Cout + o] = W[(size_t)o * rowStride + colOff + c];
    }
}

// ------------------------- cp.async 3-stage split-bf16 GEMM ----------------
// C(M,N) = A(M,Kp) * B(Kp,N);  A planes row-major, B planes n-major.
// 3 terms: Ah*Bh + Al*Bh + Ah*Bl.  Block 128x128, 8 warps (4m x 2n),
// warp tile 32x64.  Stage k16, SMEM rows padded to 48B.
__global__ __launch_bounds__(256) void gemm_async(
    const __nv_bfloat16* __restrict__ Ah,
    const __nv_bfloat16* __restrict__ Al,
    float* __restrict__ C, int Kp, int N, int acc)
{
    extern __shared__ __nv_bfloat16 dsm[];
    uint32_t sA0 = sptr(dsm);
    uint32_t sB0 = sA0 + STG * 12288;        // A region = STG*2*128*48 B

    int tid = threadIdx.x, lane = tid & 31, wid = tid >> 5;
    int warp_m = wid & 3, warp_n = wid >> 2;
    int m0 = blockIdx.y * 128, n0 = blockIdx.x * 128;
    int g = lane >> 2, t4 = lane & 3;

    float c[2][8][4];
    #pragma unroll
    for (int i = 0; i < 2; i++)
        #pragma unroll
        for (int j = 0; j < 8; j++)
            #pragma unroll
            for (int r = 0; r < 4; r++) c[i][j][r] = 0.f;

    int nch = Kp >> 4;

    int lrow = lane & 15, koffB = (lane >> 4) * 16;
    uint32_t aoff[2], boff[4];
    #pragma unroll
    for (int i = 0; i < 2; i++)
        aoff[i] = (warp_m * 32 + i * 16 + lrow) * 48 + koffB;
    #pragma unroll
    for (int q = 0; q < 4; q++)
        boff[q] = (warp_n * 64 + q * 16 + lrow) * 48 + koffB;

    auto fill_stage = [&](int s, int ch) {
        int k0 = ch * 16;
        #pragma unroll
        for (int t = 0; t < 4; t++) {
            int idx = tid + t * 256;
            int sub = idx & 511;
            int row = sub >> 2;
            int c2  = (sub >> 1) & 1;
            int pl  = sub & 1;
            if (t < 2) {
                const __nv_bfloat16* src =
                    (pl ? Al : Ah) + (size_t)(m0 + row) * Kp + k0 + c2 * 8;
                uint32_t dst = sA0 + s * 12288 + pl * 6144 + row * 48 + c2 * 16;
                CPA16(dst, src);
            } else {
                const __nv_bfloat16* src =
                    (pl ? g_wbl : g_wbh) + (size_t)(n0 + row) * Kp + k0 + c2 * 8;
                uint32_t dst = sB0 + s * 12288 + pl * 6144 + row * 48 + c2 * 16;
                CPA16(dst, src);
            }
        }
        CPA_COMMIT();
    };

    #pragma unroll
    for (int s = 0; s < STG - 1; s++) {
        if (s < nch) fill_stage(s, s);
        else CPA_COMMIT();
    }

    for (int ch = 0; ch < nch; ch++) {
        int s = ch % STG;
        CPA_WAIT1();
        __syncthreads();
        int pre = ch + STG - 1;
        if (pre < nch) fill_stage(pre % STG, pre);
        else CPA_COMMIT();

        uint32_t sAs = sA0 + s * 12288, sBs = sB0 + s * 12288;
        uint32_t ah[2][4], al[2][4];
        #pragma unroll
        for (int i = 0; i < 2; i++) {
            LDSM4(ah[i][0], ah[i][1], ah[i][2], ah[i][3], sAs + aoff[i]);
            LDSM4(al[i][0], al[i][1], al[i][2], al[i][3], sAs + 6144 + aoff[i]);
        }
        #pragma unroll
        for (int q = 0; q < 4; q++) {
            uint32_t bh0, bh1, bh2, bh3, bl0, bl1, bl2, bl3;
            LDSM4(bh0, bh1, bh2, bh3, sBs + boff[q]);
            LDSM4(bl0, bl1, bl2, bl3, sBs + 6144 + boff[q]);
            int j0 = q * 2, j1 = q * 2 + 1;
            MMA4(c[0][j0], ah[0], bh0, bh2);
            MMA4(c[0][j0], al[0], bh0, bh2);
            MMA4(c[0][j0], ah[0], bl0, bl2);
            MMA4(c[1][j0], ah[1], bh0, bh2);
            MMA4(c[1][j0], al[1], bh0, bh2);
            MMA4(c[1][j0], ah[1], bl0, bl2);
            MMA4(c[0][j1], ah[0], bh1, bh3);
            MMA4(c[0][j1], al[0], bh1, bh3);
            MMA4(c[0][j1], ah[0], bl1, bl3);
            MMA4(c[1][j1], ah[1], bh1, bh3);
            MMA4(c[1][j1], al[1], bh1, bh3);
            MMA4(c[1][j1], ah[1], bl1, bl3);
        }
    }

    #pragma unroll
    for (int i = 0; i < 2; i++) {
        int m = m0 + warp_m * 32 + i * 16 + g;
        #pragma unroll
        for (int j = 0; j < 8; j++) {
            int n = n0 + warp_n * 64 + j * 8 + t4 * 2;
            float2* p0 = (float2*)&C[(size_t)m * N + n];
            float2* p1 = (float2*)&C[(size_t)(m + 8) * N + n];
            if (acc) {
                float2 v0 = *p0, v1 = *p1;
                v0.x += c[i][j][0]; v0.y += c[i][j][1];
                v1.x += c[i][j][2]; v1.y += c[i][j][3];
                *p0 = v0; *p1 = v1;
            } else {
                *p0 = make_float2(c[i][j][0], c[i][j][1]);
                *p1 = make_float2(c[i][j][2], c[i][j][3]);
            }
        }
    }
}

// ------------------------- small FFMA GEMM (decoder, N=48) -----------------
__global__ __launch_bounds__(256) void gemm_sm(const float* __restrict__ X,
                                               float* __restrict__ C,
                                               int K, int N)
{
    __shared__ float sX[16][65];
    __shared__ float sW[16][64];
    int tx = threadIdx.x, ty = threadIdx.y;
    int tid = ty * 16 + tx;
    int m0 = blockIdx.y * 64;
    int n0 = blockIdx.x * 64;

    float accum[4][4];
    #pragma unroll
    for (int i = 0; i < 4; i++)
        #pragma unroll
        for (int j = 0; j < 4; j++) accum[i][j] = 0.f;

    for (int k0 = 0; k0 < K; k0 += 16) {
        for (int t = tid; t < 64 * 16; t += 256) {
            int m = t >> 4, k = t & 15;
            sX[k][m] = (k0 + k < K) ? X[(size_t)(m0 + m) * K + k0 + k] : 0.f;
        }
        for (int t = tid; t < 16 * 64; t += 256) {
            int k = t >> 6, n = t & 63;
            sW[k][n] = (k0 + k < K && n0 + n < N)
                     ? g_wc[(size_t)(k0 + k) * N + n0 + n] : 0.f;
        }
        __syncthreads();
        #pragma unroll
        for (int kk = 0; kk < 16; kk++) {
            float xr[4], wr[4];
            #pragma unroll
            for (int i = 0; i < 4; i++) xr[i] = sX[kk][ty * 4 + i];
            #pragma unroll
            for (int j = 0; j < 4; j++) wr[j] = sW[kk][tx * 4 + j];
            #pragma unroll
            for (int i = 0; i < 4; i++)
                #pragma unroll
                for (int j = 0; j < 4; j++)
                    accum[i][j] = fmaf(xr[i], wr[j], accum[i][j]);
        }
        __syncthreads();
    }
    #pragma unroll
    for (int i = 0; i < 4; i++) {
        int m = m0 + ty * 4 + i;
        #pragma unroll
        for (int j = 0; j < 4; j++) {
            int n = n0 + tx * 4 + j;
            if (n < N) C[(size_t)m * N + n] = accum[i][j];
        }
    }
}

// ----------- gather: sign-selected max/min + BN stats ---------------------
// sign(sc) = sign(gamma) known a-priori -> write ONE selected array.
#define GN 16
__global__ void gather_kernel(const float* __restrict__ gg, int Cout)
{
    __shared__ int sidx[GN * Kq];
    int n0 = blockIdx.x * GN;
    for (int t = threadIdx.x; t < GN * Kq; t += blockDim.x)
        sidx[t] = g_idx[(size_t)n0 * Kq + t];
    __syncthreads();

    int o  = threadIdx.x;
    int C2 = 2 * Cout;
    bool gpos = (gg[o] >= 0.f);
    float lsum = 0.f, lssq = 0.f;
    for (int g = 0; g < GN; g++) {
        int bn = n0 + g;
        int bbase = (bn >> 12) << 12;
        float a = g_ab[(size_t)bn * C2 + o];
        float mx = -CUDART_INF_F, mn = CUDART_INF_F, s = 0.f, sq = 0.f;
        #pragma unroll
        for (int k = 0; k < Kq; k++) {
            int j = sidx[g * Kq + k];
            float v = g_ab[(size_t)(bbase + j) * C2 + Cout + o];
            mx = fmaxf(mx, v); mn = fminf(mn, v);
            s += v; sq = fmaf(v, v, sq);
        }
        g_ysel[(size_t)bn * Cout + o] = a + (gpos ? mx : mn);
        lsum += fmaf((float)Kq, a, s);
        lssq += (float)Kq * a * a + 2.f * a * s + sq;
    }
    atomicAdd(&g_stats[o], lsum);
    atomicAdd(&g_stats[512 + o], lssq);
}

// ------------------------- column stats (decoder BN) -----------------------
__global__ void colstats_kernel(const float* __restrict__ Y, int C, int Mrows,
                                float* __restrict__ stats)
{
    __shared__ float ss[256];
    __shared__ float sq[256];
    int o = blockIdx.x;
    float s = 0.f, q = 0.f;
    for (int m = threadIdx.x; m < Mrows; m += 256) {
        float v = Y[(size_t)m * C + o];
        s += v; q = fmaf(v, v, q);
    }
    ss[threadIdx.x] = s; sq[threadIdx.x] = q;
    __syncthreads();
    for (int st = 128; st; st >>= 1) {
        if (threadIdx.x < st) {
            ss[threadIdx.x] += ss[threadIdx.x + st];
            sq[threadIdx.x] += sq[threadIdx.x + st];
        }
        __syncthreads();
    }
    if (threadIdx.x == 0) { stats[o] = ss[0]; stats[512 + o] = sq[0]; }
}

// ------------------------- BN + ReLU + plane split -------------------------
__global__ void bnrelu_kernel(const float* __restrict__ ysel,
                              const float* __restrict__ gg,
                              const float* __restrict__ bb,
                              float* __restrict__ outp,
                              __nv_bfloat16* __restrict__ ph,
                              __nv_bfloat16* __restrict__ pl,
                              const float* __restrict__ stats,
                              int C, float invCnt, int total)
{
    for (int i = blockIdx.x * blockDim.x + threadIdx.x; i < total;
         i += gridDim.x * blockDim.x) {
        int o = i % C;
        float mean = stats[o] * invCnt;
        float var  = fmaf(-mean, mean, stats[512 + o] * invCnt);
        float sc   = gg[o] * rsqrtf(var + 1e-5f);
        float sh   = fmaf(-mean, sc, bb[o]);
        float r    = fmaxf(fmaf(sc, ysel[i], sh), 0.f);
        if (outp) outp[i] = r;
        __nv_bfloat16 h, l;
        bf16_split(r, h, l);
        ph[i] = h; pl[i] = l;
    }
}

// ------------------------- global max/mean pool (2-stage) ------------------
__global__ void hreduce1_kernel()
{
    int b = blockIdx.y, chunk = blockIdx.x, o = threadIdx.x;
    const float* f = g_fused + ((size_t)b * Nq + chunk * 128) * 256 + o;
    float mx = -CUDART_INF_F, s = 0.f;
    for (int n = 0; n < 128; n++) {
        float v = f[(size_t)n * 256];
        mx = fmaxf(mx, v); s += v;
    }
    g_hpart[0][b][chunk][o] = mx;
    g_hpart[1][b][chunk][o] = s;
}

__global__ void hreduce2_kernel()
{
    int b = blockIdx.x, o = threadIdx.x;
    float mx = -CUDART_INF_F, s = 0.f;
    #pragma unroll
    for (int c = 0; c < 32; c++) {
        mx = fmaxf(mx, g_hpart[0][b][c][o]);
        s += g_hpart[1][b][c][o];
    }
    g_h[b * 512 + o]       = mx;
    g_h[b * 512 + 256 + o] = s * (1.f / Nq);
}

// ------------------------- classifier head ---------------------------------
__global__ void cls1_kernel(const float* __restrict__ W,
                            const float* __restrict__ gg,
                            const float* __restrict__ bb)
{
    int o = threadIdx.x;
    float y[4];
    #pragma unroll
    for (int b = 0; b < 4; b++) {
        float s = 0.f;
        const float* wr = W + (size_t)o * 512;
        const float* hr = g_h + b * 512;
        for (int c = 0; c < 512; c++) s = fmaf(wr[c], hr[c], s);
        y[b] = s;
    }
    float mean = 0.25f * (y[0] + y[1] + y[2] + y[3]);
    float ssq  = y[0]*y[0] + y[1]*y[1] + y[2]*y[2] + y[3]*y[3];
    float var  = fmaf(-mean, mean, 0.25f * ssq);
    float sc   = gg[o] * rsqrtf(var + 1e-5f);
    float sh   = fmaf(-mean, sc, bb[o]);
    #pragma unroll
    for (int b = 0; b < 4; b++)
        g_h2[b * 256 + o] = fmaxf(fmaf(sc, y[b], sh), 0.f);
}

__global__ void cls2_kernel(const float* __restrict__ W, float* __restrict__ out)
{
    int t = threadIdx.x;
    if (t < 160) {
        int b = t / 40, o = t % 40;
        float s = 0.f;
        for (int c = 0; c < 256; c++)
            s = fmaf(W[(size_t)o * 256 + c], g_h2[b * 256 + c], s);
        out[b * 40 + o] = s;
    }
}

// ------------------------- host launch sequence ----------------------------
extern "C" void kernel_launch(void* const* d_in, const int* in_sizes, int n_in,
                              void* d_out, int out_size)
{
    const float* x     = (const float*)d_in[0];
    const float* w1    = (const float*)d_in[2];
    const float* g1    = (const float*)d_in[3];
    const float* b1    = (const float*)d_in[4];
    const float* w2    = (const float*)d_in[5];
    const float* g2    = (const float*)d_in[6];
    const float* b2    = (const float*)d_in[7];
    const float* w3    = (const float*)d_in[8];
    const float* g3    = (const float*)d_in[9];
    const float* b3    = (const float*)d_in[10];
    const float* w4    = (const float*)d_in[11];
    const float* g4    = (const float*)d_in[12];
    const float* b4    = (const float*)d_in[13];
    const float* dec_w = (const float*)d_in[14];
    const float* dec_g = (const float*)d_in[15];
    const float* dec_b = (const float*)d_in[16];
    const float* fus_w = (const float*)d_in[17];
    const float* cw1   = (const float*)d_in[18];
    const float* cg    = (const float*)d_in[19];
    const float* cb    = (const float*)d_in[20];
    const float* cw2   = (const float*)d_in[21];
    float* out = (float*)d_out;

    static int smem_set = 0;
    if (!smem_set) {
        cudaFuncSetAttribute(gemm_async,
            cudaFuncAttributeMaxDynamicSharedMemorySize, 2 * STG * 12288);
        smem_set = 1;
    }
    const int GSM = 2 * STG * 12288;   // 73728 B dynamic smem

    void *p_ab, *p_ysel, *p_act1, *p_low, *p_fused, *p_stats1, *p_stats2,
         *p_ph, *p_pl, *p_lowh, *p_lowl;
    cudaGetSymbolAddress(&p_ab,     g_ab);
    cudaGetSymbolAddress(&p_ysel,   g_ysel);
    cudaGetSymbolAddress(&p_act1,   g_act1);
    cudaGetSymbolAddress(&p_low,    g_low);
    cudaGetSymbolAddress(&p_fused,  g_fused);
    cudaGetSymbolAddress(&p_stats1, g_stats);
    cudaGetSymbolAddress(&p_stats2, g_stats2);
    cudaGetSymbolAddress(&p_ph,     g_ph);
    cudaGetSymbolAddress(&p_pl,     g_pl);
    cudaGetSymbolAddress(&p_lowh,   g_lowh);
    cudaGetSymbolAddress(&p_lowl,   g_lowl);

    const __nv_bfloat16* ph = (const __nv_bfloat16*)p_ph;
    const __nv_bfloat16* pl = (const __nv_bfloat16*)p_pl;
    const float invEdge = 1.f / CNT_EDGE;
    const dim3 tb16(16, 16);

    transpose_kernel<<<(BNT * 16 + 255) / 256, 256>>>(x);
    knn_kernel<<<128, 256>>>(x);

    // ---- EdgeConv 1: Cin=3 (Kp=16), Cout=64 (N=128) ----
    prep_edge_wb<<<(128 * 16 + 1023) / 256, 256>>>(w1, 3, 64, 16);
    gemm_async<<<dim3(1, 128), 256, GSM>>>(ph, pl, (float*)p_ab, 16, 128, 0);
    gather_kernel<<<BNT / GN, 64>>>(g1, 64);
    bnrelu_kernel<<<(BNT * 64 + 255) / 256, 256>>>((const float*)p_ysel,
        g1, b1, (float*)p_act1, (__nv_bfloat16*)p_ph, (__nv_bfloat16*)p_pl,
        (const float*)p_stats1, 64, invEdge, BNT * 64);

    // ---- EdgeConv 2: Kp=64, Cout=128 (N=256) ----
    prep_edge_wb<<<(256 * 64 + 255) / 256, 256>>>(w2, 64, 128, 64);
    gemm_async<<<dim3(2, 128), 256, GSM>>>(ph, pl, (float*)p_ab, 64, 256, 0);
    gather_kernel<<<BNT / GN, 128>>>(g2, 128);
    bnrelu_kernel<<<(BNT * 128 + 255) / 256, 256>>>((const float*)p_ysel,
        g2, b2, nullptr, (__nv_bfloat16*)p_ph, (__nv_bfloat16*)p_pl,
        (const float*)p_stats1, 128, invEdge, BNT * 128);

    // ---- EdgeConv 3: Kp=128, Cout=256 (N=512) ----
    prep_edge_wb<<<(512 * 128 + 255) / 256, 256>>>(w3, 128, 256, 128);
    gemm_async<<<dim3(4, 128), 256, GSM>>>(ph, pl, (float*)p_ab, 128, 512, 0);
    gather_kernel<<<BNT / GN, 256>>>(g3, 256);
    bnrelu_kernel<<<(BNT * 256 + 255) / 256, 256>>>((const float*)p_ysel,
        g3, b3, nullptr, (__nv_bfloat16*)p_ph, (__nv_bfloat16*)p_pl,
        (const float*)p_stats1, 256, invEdge, BNT * 256);

    // ---- EdgeConv 4: Kp=256, Cout=256 (N=512) ----
    prep_edge_wb<<<(512 * 256 + 255) / 256, 256>>>(w4, 256, 256, 256);
    gemm_async<<<dim3(4, 128), 256, GSM>>>(ph, pl, (float*)p_ab, 256, 512, 0);
    gather_kernel<<<BNT / GN, 256>>>(g4, 256);
    bnrelu_kernel<<<(BNT * 256 + 255) / 256, 256>>>((const float*)p_ysel,
        g4, b4, nullptr, (__nv_bfloat16*)p_ph, (__nv_bfloat16*)p_pl,
        (const float*)p_stats1, 256, invEdge, BNT * 256);
    // g_ph/g_pl now hold out4 planes (Kp=256)

    // ---- decoder: low = relu(bn(dec_w @ out1)) ----
    prep_plain_w<<<(64 * 48 + 255) / 256, 256>>>(dec_w, 64, 48, 64, 0);
    gemm_sm<<<dim3(1, 256), tb16>>>((const float*)p_act1, (float*)p_low, 64, 48);
    colstats_kernel<<<48, 256>>>((const float*)p_low, 48, BNT, (float*)p_stats2);
    bnrelu_kernel<<<(BNT * 48 + 255) / 256, 256>>>((const float*)p_low,
        dec_g, dec_b, nullptr, (__nv_bfloat16*)p_lowh, (__nv_bfloat16*)p_lowl,
        (const float*)p_stats2, 48, 1.f / BNT, BNT * 48);

    // ---- fusion: fused = fus_w @ concat([out4, low]) ----
    prep_plain_wb<<<(256 * 256 + 255) / 256, 256>>>(fus_w, 256, 256, 304, 0, 256);
    gemm_async<<<dim3(2, 128), 256, GSM>>>(ph, pl, (float*)p_fused, 256, 256, 0);
    prep_plain_wb<<<(256 * 48 + 255) / 256, 256>>>(fus_w, 48, 256, 304, 256, 48);
    gemm_async<<<dim3(2, 128), 256, GSM>>>((const __nv_bfloat16*)p_lowh,
        (const __nv_bfloat16*)p_lowl, (float*)p_fused, 48, 256, 1);

    // ---- head ----
    hreduce1_kernel<<<dim3(32, Bq), 256>>>();
    hreduce2_kernel<<<Bq, 256>>>();
    cls1_kernel<<<1, 256>>>(cw1, cg, cb);
    cls2_kernel<<<1, 192>>>(cw2, out);
}